// round 7
// baseline (speedup 1.0000x reference)
#include <cuda_runtime.h>
#include <cuda_bf16.h>
#include <math.h>

#define T_STEPS 16384
#define N_DIM   256
#define M_DIM   512
#define G3      1536   // 3*M
#define NADDR   512    // K_MEM+1
#define L_OUT   256

#define CSZ     16     // cluster size (CTAs)
#define DPC     32     // h-dims per CTA (512/16)
#define NTHR    512

// ---------------- device scratch (static, no allocation) ----------------
__device__ __align__(16) float d_Gi[T_STEPS * G3];     // X @ W_ih^T + b_ih
__device__ __align__(16) float d_H [T_STEPS * M_DIM];  // h_out history
__device__ __align__(16) float d_M [NADDR * M_DIM];    // memory rows (write-once)

// ---------------- helpers ----------------
__device__ __forceinline__ void stcg_f(float* p, float v) {
    asm volatile("st.global.cg.f32 [%0], %1;" :: "l"(p), "f"(v) : "memory");
}
__device__ __forceinline__ void dsmem_st_u64(unsigned long long* localPtr, unsigned rank,
                                             unsigned long long v) {
    unsigned laddr = (unsigned)__cvta_generic_to_shared(localPtr);
    unsigned raddr;
    asm volatile("mapa.shared::cluster.u32 %0, %1, %2;" : "=r"(raddr) : "r"(laddr), "r"(rank));
    asm volatile("st.shared::cluster.u64 [%0], %1;" :: "r"(raddr), "l"(v) : "memory");
}
__device__ __forceinline__ unsigned long long ldvol_sm_u64(const unsigned long long* p) {
    unsigned a = (unsigned)__cvta_generic_to_shared(p);
    unsigned long long v;
    asm volatile("ld.volatile.shared.u64 %0, [%1];" : "=l"(v) : "r"(a) : "memory");
    return v;
}
#define CLUSTER_SYNC() do { \
    asm volatile("barrier.cluster.arrive.aligned;" ::: "memory"); \
    asm volatile("barrier.cluster.wait.aligned;"   ::: "memory"); } while (0)

// ---------------- textbook 32x32 tiled NT GEMM (known good) ----------------
__global__ __launch_bounds__(1024) void gemm32_nt(
    const float* __restrict__ A, const float* __restrict__ B,
    const float* __restrict__ bias, float* __restrict__ C,
    int M, int N, int K)
{
    __shared__ float As[32][33];
    __shared__ float Bs[32][33];
    const int bm = blockIdx.y * 32;
    const int bn = blockIdx.x * 32;
    const int tx = threadIdx.x;
    const int ty = threadIdx.y;
    float acc = 0.f;
    for (int k0 = 0; k0 < K; k0 += 32) {
        As[ty][tx] = A[(size_t)(bm + ty) * K + k0 + tx];
        Bs[ty][tx] = B[(size_t)(bn + ty) * K + k0 + tx];
        __syncthreads();
        #pragma unroll
        for (int k = 0; k < 32; k++)
            acc = fmaf(As[ty][k], Bs[tx][k], acc);
        __syncthreads();
    }
    C[(size_t)(bm + ty) * N + bn + tx] = acc + bias[bn + tx];
}

// ---------------- clustered recurrent kernel, barrier-free hot loop ----------------
// One 16-CTA cluster. CTA c owns h-dims [32c,32c+32); warp w owns dims
// d0=32c+w, d1=32c+16+w. Gate-r W rows + C_w rows in registers; gates z,n in SMEM.
// All cross-CTA sync via tagged 64-bit DSMEM words + local SMEM polling.
// Arithmetic chains verbatim round-4/6 -> trajectory bit-identical.
__global__ __launch_bounds__(NTHR, 1) void dmm_rec(
    const float* __restrict__ h0,
    const float* __restrict__ W_hh,
    const float* __restrict__ b_hh,
    const float* __restrict__ C_w,
    const float* __restrict__ C_b)
{
    extern __shared__ float W_sm[];               // [2*DPC][512]: gate z rows, gate n rows
    __shared__ float h_sm[M_DIM];
    __shared__ float hn_f_sm[M_DIM];
    __shared__ unsigned long long hn64_sm[M_DIM];   // [val|tag|0] tagged h_new (DSMEM target)
    __shared__ unsigned long long wkey_sm[16];
    __shared__ unsigned long long ckey_sm[CSZ];     // [u|tag|1023-d] per-CTA keys (DSMEM target)
    __shared__ unsigned char written_sm[NADDR];
    __shared__ int dec_sm;

    const int c   = blockIdx.x;                   // == cluster rank (single cluster)
    const int tid = threadIdx.x;
    const int w   = tid >> 5;
    const int l   = tid & 31;
    const int d0  = DPC * c + w;
    const int d1  = DPC * c + 16 + w;
    const int myd = (l < 16) ? d0 : d1;

    // ---- one-time init ----
    for (int idx = tid; idx < 2 * DPC * M_DIM; idx += NTHR) {
        int g   = idx >> 14;          // 0 -> gate z, 1 -> gate n
        int rem = idx & 16383;
        int lr  = rem >> 9;
        int col = rem & 511;
        W_sm[idx] = W_hh[(size_t)((g + 1) * M_DIM + DPC * c + lr) * M_DIM + col];
    }
    h_sm[tid] = h0[tid];
    hn64_sm[tid] = (0xFFFFull << 16);             // tag = 0xFFFF (never matches)
    written_sm[tid] = 0;
    if (tid < CSZ) ckey_sm[tid] = (0xFFFFull << 16);

    float4 wr0[4], wr1[4], cw0[4], cw1[4];
    #pragma unroll
    for (int cch = 0; cch < 4; cch++) {
        wr0[cch] = *(const float4*)&W_hh[(size_t)d0 * M_DIM + cch * 128 + 4 * l];
        wr1[cch] = *(const float4*)&W_hh[(size_t)d1 * M_DIM + cch * 128 + 4 * l];
        cw0[cch] = *(const float4*)&C_w [(size_t)d0 * M_DIM + cch * 128 + 4 * l];
        cw1[cch] = *(const float4*)&C_w [(size_t)d1 * M_DIM + cch * 128 + 4 * l];
    }
    const float cb0 = C_b[d0], cb1 = C_b[d1];
    const float bhr = b_hh[myd], bhz = b_hh[M_DIM + myd], bhn = b_hh[2 * M_DIM + myd];

    float gir = 0.f, giz = 0.f, gin = 0.f;
    if ((l & 15) == 0) {
        gir = __ldg(&d_Gi[myd]);
        giz = __ldg(&d_Gi[M_DIM + myd]);
        gin = __ldg(&d_Gi[2 * M_DIM + myd]);
    }

    __syncthreads();
    CLUSTER_SYNC();   // all inits visible before any DSMEM traffic

    for (int t = 0; t < T_STEPS; t++) {
        const unsigned tagv = (unsigned)(t & 0xFFFF);

        // ================= phase 1: GEMV + gates =================
        const float hprev = h_sm[myd];
        float4 hv[4];
        #pragma unroll
        for (int cch = 0; cch < 4; cch++) hv[cch] = *(const float4*)&h_sm[cch * 128 + 4 * l];

        auto dot_sm = [&](const float* __restrict__ row) -> float {
            float acc = 0.f;
            #pragma unroll
            for (int cch = 0; cch < 4; cch++) {
                float4 wv = *(const float4*)&row[cch * 128 + 4 * l];
                acc = fmaf(wv.x, hv[cch].x, fmaf(wv.y, hv[cch].y,
                      fmaf(wv.z, hv[cch].z, fmaf(wv.w, hv[cch].w, acc))));
            }
            #pragma unroll
            for (int o = 16; o > 0; o >>= 1) acc += __shfl_xor_sync(0xFFFFFFFFu, acc, o);
            return acc;
        };
        auto dot_rg = [&](const float4* wreg) -> float {
            float acc = 0.f;
            #pragma unroll
            for (int cch = 0; cch < 4; cch++) {
                acc = fmaf(wreg[cch].x, hv[cch].x, fmaf(wreg[cch].y, hv[cch].y,
                      fmaf(wreg[cch].z, hv[cch].z, fmaf(wreg[cch].w, hv[cch].w, acc))));
            }
            #pragma unroll
            for (int o = 16; o > 0; o >>= 1) acc += __shfl_xor_sync(0xFFFFFFFFu, acc, o);
            return acc;
        };
        const float a0z = dot_sm(&W_sm[(0 * DPC + w)      * M_DIM]);
        const float a0n = dot_sm(&W_sm[(1 * DPC + w)      * M_DIM]);
        const float a1z = dot_sm(&W_sm[(0 * DPC + 16 + w) * M_DIM]);
        const float a1n = dot_sm(&W_sm[(1 * DPC + 16 + w) * M_DIM]);
        const float a0r = dot_rg(wr0);
        const float a1r = dot_rg(wr1);

        float hnewv = 0.f;
        if (l == 0) {
            float hr = a0r + bhr, hz = a0z + bhz, hn = a0n + bhn;
            float rg = 1.f / (1.f + expf(-(gir + hr)));
            float zg = 1.f / (1.f + expf(-(giz + hz)));
            float ng = tanhf(gin + rg * hn);
            hnewv = (1.f - zg) * ng + zg * hprev;
        } else if (l == 16) {
            float hr = a1r + bhr, hz = a1z + bhz, hn = a1n + bhn;
            float rg = 1.f / (1.f + expf(-(gir + hr)));
            float zg = 1.f / (1.f + expf(-(giz + hz)));
            float ng = tanhf(gin + rg * hn);
            hnewv = (1.f - zg) * ng + zg * hprev;
        }
        const float v0 = __shfl_sync(0xFFFFFFFFu, hnewv, 0);
        const float v1 = __shfl_sync(0xFFFFFFFFu, hnewv, 16);

        // broadcast tagged h_new word to every CTA (lane -> rank l&15)
        {
            float val = (l < 16) ? v0 : v1;
            unsigned long long pkt =
                ((unsigned long long)__float_as_uint(val) << 32) |
                ((unsigned long long)tagv << 16);
            dsmem_st_u64(&hn64_sm[myd], (unsigned)(l & 15), pkt);
        }

        // prefetch Gi(t+1) (latency hides under the hn handshake)
        float ngir = 0.f, ngiz = 0.f, ngin = 0.f;
        if ((l & 15) == 0 && t + 1 < T_STEPS) {
            const float* g = &d_Gi[(size_t)(t + 1) * G3];
            ngir = __ldg(&g[myd]);
            ngiz = __ldg(&g[M_DIM + myd]);
            ngin = __ldg(&g[2 * M_DIM + myd]);
        }

        // ================= phase 2: poll h_new, logits, CTA key =================
        {
            unsigned long long pkt;
            do { pkt = ldvol_sm_u64(&hn64_sm[tid]); }
            while (((unsigned)(pkt >> 16) & 0xFFFFu) != tagv);
            hn_f_sm[tid] = __uint_as_float((unsigned)(pkt >> 32));
        }
        __syncthreads();

        float4 nv[4];
        #pragma unroll
        for (int cch = 0; cch < 4; cch++) nv[cch] = *(const float4*)&hn_f_sm[cch * 128 + 4 * l];
        float acc0 = 0.f, acc1 = 0.f;
        #pragma unroll
        for (int cch = 0; cch < 4; cch++) {
            acc0 = fmaf(cw0[cch].x, nv[cch].x, fmaf(cw0[cch].y, nv[cch].y,
                   fmaf(cw0[cch].z, nv[cch].z, fmaf(cw0[cch].w, nv[cch].w, acc0))));
        }
        #pragma unroll
        for (int o = 16; o > 0; o >>= 1) acc0 += __shfl_xor_sync(0xFFFFFFFFu, acc0, o);
        #pragma unroll
        for (int cch = 0; cch < 4; cch++) {
            acc1 = fmaf(cw1[cch].x, nv[cch].x, fmaf(cw1[cch].y, nv[cch].y,
                   fmaf(cw1[cch].z, nv[cch].z, fmaf(cw1[cch].w, nv[cch].w, acc1))));
        }
        #pragma unroll
        for (int o = 16; o > 0; o >>= 1) acc1 += __shfl_xor_sync(0xFFFFFFFFu, acc1, o);

        if (l == 0) {
            unsigned int u0 = __float_as_uint(acc0 + cb0);
            u0 ^= (u0 & 0x80000000u) ? 0xFFFFFFFFu : 0x80000000u;
            unsigned long long k0 = ((unsigned long long)u0 << 32) |
                                    ((unsigned long long)tagv << 16) |
                                    (unsigned)(1023 - d0);
            unsigned int u1 = __float_as_uint(acc1 + cb1);
            u1 ^= (u1 & 0x80000000u) ? 0xFFFFFFFFu : 0x80000000u;
            unsigned long long k1 = ((unsigned long long)u1 << 32) |
                                    ((unsigned long long)tagv << 16) |
                                    (unsigned)(1023 - d1);
            wkey_sm[w] = (k0 > k1) ? k0 : k1;
        }
        __syncthreads();
        if (w == 0) {
            unsigned long long k = (l < 16) ? wkey_sm[l] : 0ull;
            #pragma unroll
            for (int o = 16; o > 0; o >>= 1) {
                unsigned long long ok = __shfl_xor_sync(0xFFFFFFFFu, k, o);
                if (ok > k) k = ok;
            }
            if (l < CSZ) dsmem_st_u64(&ckey_sm[c], (unsigned)l, k);
        }

        // ================= phase 3: poll keys, decide, memory op =================
        if (w == 0) {
            unsigned long long k = 0ull;
            if (l < CSZ) {
                do { k = ldvol_sm_u64(&ckey_sm[l]); }
                while (((unsigned)(k >> 16) & 0xFFFFu) != tagv);
            }
            #pragma unroll
            for (int o = 16; o > 0; o >>= 1) {
                unsigned long long ok = __shfl_xor_sync(0xFFFFFFFFu, k, o);
                if (ok > k) k = ok;
            }
            if (l == 0) {
                int q   = 1023 - (int)(k & 0xFFFFull);
                int has = (q > 0) && (written_sm[q] != 0);
                if (q > 0) written_sm[q] = 1;
                dec_sm = (q << 1) | has;
            }
        }
        __syncthreads();
        const int dec = dec_sm;
        const int q   = dec >> 1;
        const int has = dec & 1;

        __threadfence();   // order vs d_M stores from other SMs (paranoia belt)
        float hout;
        if (has) {
            hout = __ldg(&d_M[(size_t)q * M_DIM + tid]);   // write-once row, >=1 step old
        } else {
            hout = hn_f_sm[tid];
            if (q > 0 && c == (q & (CSZ - 1)))
                stcg_f(&d_M[(size_t)q * M_DIM + tid], hout);
        }
        __threadfence();   // d_M store drained before next step's DSMEM signaling

        h_sm[tid] = hout;
        if (c == 0) d_H[(size_t)t * M_DIM + tid] = hout;

        gir = ngir; giz = ngiz; gin = ngin;
        __syncthreads();
    }

    CLUSTER_SYNC();   // no CTA exits while peers may still touch its SMEM
}

extern "C" void kernel_launch(void* const* d_in, const int* in_sizes, int n_in,
                              void* d_out, int out_size)
{
    const float* X    = (const float*)d_in[0];
    const float* h0   = (const float*)d_in[1];
    const float* W_ih = (const float*)d_in[2];
    const float* W_hh = (const float*)d_in[3];
    const float* b_ih = (const float*)d_in[4];
    const float* b_hh = (const float*)d_in[5];
    const float* C_w  = (const float*)d_in[6];
    const float* C_b  = (const float*)d_in[7];
    const float* V_w  = (const float*)d_in[8];
    const float* V_b  = (const float*)d_in[9];
    float* Y = (float*)d_out;

    float* Gi; cudaGetSymbolAddress((void**)&Gi, d_Gi);
    float* H;  cudaGetSymbolAddress((void**)&H,  d_H);

    // 1) Gi = X @ W_ih^T + b_ih
    {
        dim3 blk(32, 32), grid(G3 / 32, T_STEPS / 32);
        gemm32_nt<<<grid, blk>>>(X, W_ih, b_ih, Gi, T_STEPS, G3, N_DIM);
    }
    // 2) clustered recurrent loop (one 16-CTA cluster, polling sync)
    {
        const int smem = 2 * DPC * M_DIM * (int)sizeof(float);   // 131072
        cudaFuncSetAttribute(dmm_rec, cudaFuncAttributeNonPortableClusterSizeAllowed, 1);
        cudaFuncSetAttribute(dmm_rec, cudaFuncAttributeMaxDynamicSharedMemorySize, smem);
        cudaLaunchConfig_t cfg = {};
        cfg.gridDim  = dim3(CSZ, 1, 1);
        cfg.blockDim = dim3(NTHR, 1, 1);
        cfg.dynamicSmemBytes = smem;
        cfg.stream = 0;
        cudaLaunchAttribute at[1];
        at[0].id = cudaLaunchAttributeClusterDimension;
        at[0].val.clusterDim.x = CSZ;
        at[0].val.clusterDim.y = 1;
        at[0].val.clusterDim.z = 1;
        cfg.attrs = at;
        cfg.numAttrs = 1;
        cudaLaunchKernelEx(&cfg, dmm_rec, h0, W_hh, b_hh, C_w, C_b);
    }
    // 3) Y = H @ V_w^T + V_b
    {
        dim3 blk(32, 32), grid(L_OUT / 32, T_STEPS / 32);
        gemm32_nt<<<grid, blk>>>(H, V_w, V_b, Y, T_STEPS, L_OUT, M_DIM);
    }
}

// round 8
// speedup vs baseline: 1.1925x; 1.1925x over previous
#include <cuda_runtime.h>
#include <cuda_bf16.h>
#include <math.h>

#define T_STEPS 16384
#define N_DIM   256
#define M_DIM   512
#define G3      1536   // 3*M
#define NADDR   512    // K_MEM+1
#define L_OUT   256

#define CSZ     16     // cluster size (CTAs)
#define DPC     32     // h-dims per CTA (512/16)
#define NTHR    512

// ---------------- device scratch (static, no allocation) ----------------
__device__ __align__(16) float d_Gi[T_STEPS * G3];     // X @ W_ih^T + b_ih
__device__ __align__(16) float d_H [T_STEPS * M_DIM];  // h_out history
__device__ __align__(16) float d_M [NADDR * M_DIM];    // memory rows (write-once)
__device__ __align__(16) float d_Gc[NADDR * G3];       // cached gh vectors: [q][3*d + gate]

// ---------------- helpers ----------------
__device__ __forceinline__ float ldcg_f(const float* p) {
    float v; asm volatile("ld.global.cg.f32 %0, [%1];" : "=f"(v) : "l"(p) : "memory"); return v;
}
__device__ __forceinline__ void dsmem_st_f32(float* localPtr, unsigned rank, float v) {
    unsigned laddr = (unsigned)__cvta_generic_to_shared(localPtr);
    unsigned raddr;
    asm volatile("mapa.shared::cluster.u32 %0, %1, %2;" : "=r"(raddr) : "r"(laddr), "r"(rank));
    asm volatile("st.shared::cluster.f32 [%0], %1;" :: "r"(raddr), "f"(v) : "memory");
}
__device__ __forceinline__ void dsmem_st_u64(unsigned long long* localPtr, unsigned rank,
                                             unsigned long long v) {
    unsigned laddr = (unsigned)__cvta_generic_to_shared(localPtr);
    unsigned raddr;
    asm volatile("mapa.shared::cluster.u32 %0, %1, %2;" : "=r"(raddr) : "r"(laddr), "r"(rank));
    asm volatile("st.shared::cluster.u64 [%0], %1;" :: "r"(raddr), "l"(v) : "memory");
}
#define CLUSTER_ARRIVE() asm volatile("barrier.cluster.arrive.aligned;" ::: "memory")
#define CLUSTER_WAIT()   asm volatile("barrier.cluster.wait.aligned;"   ::: "memory")
#define CLUSTER_SYNC()   do { CLUSTER_ARRIVE(); CLUSTER_WAIT(); } while (0)

// ---------------- textbook 32x32 tiled NT GEMM (known good) ----------------
__global__ __launch_bounds__(1024) void gemm32_nt(
    const float* __restrict__ A, const float* __restrict__ B,
    const float* __restrict__ bias, float* __restrict__ C,
    int M, int N, int K)
{
    __shared__ float As[32][33];
    __shared__ float Bs[32][33];
    const int bm = blockIdx.y * 32;
    const int bn = blockIdx.x * 32;
    const int tx = threadIdx.x;
    const int ty = threadIdx.y;
    float acc = 0.f;
    for (int k0 = 0; k0 < K; k0 += 32) {
        As[ty][tx] = A[(size_t)(bm + ty) * K + k0 + tx];
        Bs[ty][tx] = B[(size_t)(bn + ty) * K + k0 + tx];
        __syncthreads();
        #pragma unroll
        for (int k = 0; k < 32; k++)
            acc = fmaf(As[ty][k], Bs[tx][k], acc);
        __syncthreads();
    }
    C[(size_t)(bm + ty) * N + bn + tx] = acc + bias[bn + tx];
}

// ---------------- clustered recurrent kernel with gh speculation ----------------
// One 16-CTA cluster, 512 thr/CTA. Warp w owns dims d0=32c+w, d1=32c+16+w and
// logit addresses d0,d1. Gate-r W rows + C_w rows in registers; z,n rows in SMEM.
// Per step: gates(select) -> hn DSMEM bcast -> [sync1] -> logits+keys -> [arrive2]
// -> speculative W_hh@hn (hides wait2) -> [wait2] -> decision -> select/cache.
// All selected values identical to recomputation -> trajectory bit-identical to r4/6.
__global__ __launch_bounds__(NTHR, 1) void dmm_rec(
    const float* __restrict__ h0,
    const float* __restrict__ W_hh,
    const float* __restrict__ b_hh,
    const float* __restrict__ C_w,
    const float* __restrict__ C_b)
{
    extern __shared__ float W_sm[];               // [2*DPC][512]: gate z rows, gate n rows
    __shared__ float hn_sm[2][M_DIM];             // broadcast h_new (DSMEM target); [1] = h0 at boot
    __shared__ unsigned long long wkey_sm[16];
    __shared__ unsigned long long ckey_sm[CSZ];   // per-CTA keys (DSMEM target)
    __shared__ unsigned char written_sm[NADDR];
    __shared__ int dec_sm;

    const int c   = blockIdx.x;                   // cluster rank (single cluster)
    const int tid = threadIdx.x;
    const int w   = tid >> 5;
    const int l   = tid & 31;
    const int ml  = l & 15;
    const int d0  = DPC * c + w;
    const int d1  = DPC * c + 16 + w;
    const int myd = (l < 16) ? d0 : d1;

    // ---- one-time init ----
    for (int idx = tid; idx < 2 * DPC * M_DIM; idx += NTHR) {
        int g   = idx >> 14;          // 0 -> gate z, 1 -> gate n
        int rem = idx & 16383;
        int lr  = rem >> 9;
        int col = rem & 511;
        W_sm[idx] = W_hh[(size_t)((g + 1) * M_DIM + DPC * c + lr) * M_DIM + col];
    }
    written_sm[tid] = 0;

    float4 wr0[4], wr1[4], cw0[4], cw1[4];
    #pragma unroll
    for (int cch = 0; cch < 4; cch++) {
        wr0[cch] = *(const float4*)&W_hh[(size_t)d0 * M_DIM + cch * 128 + 4 * l];
        wr1[cch] = *(const float4*)&W_hh[(size_t)d1 * M_DIM + cch * 128 + 4 * l];
        cw0[cch] = *(const float4*)&C_w [(size_t)d0 * M_DIM + cch * 128 + 4 * l];
        cw1[cch] = *(const float4*)&C_w [(size_t)d1 * M_DIM + cch * 128 + 4 * l];
    }
    const float cb0 = C_b[d0], cb1 = C_b[d1];
    const float bhr = b_hh[myd], bhz = b_hh[M_DIM + myd], bhn = b_hh[2 * M_DIM + myd];

    // ---- bootstrap: spec dots on h0 (same chains as the in-loop GEMV) ----
    if (tid < M_DIM) hn_sm[1][tid] = h0[tid];
    __syncthreads();

    float4 nv[4];
    #pragma unroll
    for (int cch = 0; cch < 4; cch++) nv[cch] = *(const float4*)&hn_sm[1][cch * 128 + 4 * l];

    auto dot_sm = [&](const float* __restrict__ row) -> float {
        float acc = 0.f;
        #pragma unroll
        for (int cch = 0; cch < 4; cch++) {
            float4 wv = *(const float4*)&row[cch * 128 + 4 * l];
            acc = fmaf(wv.x, nv[cch].x, fmaf(wv.y, nv[cch].y,
                  fmaf(wv.z, nv[cch].z, fmaf(wv.w, nv[cch].w, acc))));
        }
        #pragma unroll
        for (int o = 16; o > 0; o >>= 1) acc += __shfl_xor_sync(0xFFFFFFFFu, acc, o);
        return acc;
    };
    auto dot_rg = [&](const float4* wreg) -> float {
        float acc = 0.f;
        #pragma unroll
        for (int cch = 0; cch < 4; cch++) {
            acc = fmaf(wreg[cch].x, nv[cch].x, fmaf(wreg[cch].y, nv[cch].y,
                  fmaf(wreg[cch].z, nv[cch].z, fmaf(wreg[cch].w, nv[cch].w, acc))));
        }
        #pragma unroll
        for (int o = 16; o > 0; o >>= 1) acc += __shfl_xor_sync(0xFFFFFFFFu, acc, o);
        return acc;
    };

    float s0z = dot_sm(&W_sm[(0 * DPC + w)      * M_DIM]);
    float s0n = dot_sm(&W_sm[(1 * DPC + w)      * M_DIM]);
    float s1z = dot_sm(&W_sm[(0 * DPC + 16 + w) * M_DIM]);
    float s1n = dot_sm(&W_sm[(1 * DPC + 16 + w) * M_DIM]);
    float s0r = dot_rg(wr0);
    float s1r = dot_rg(wr1);

    // per-lane gate inputs for t = 0
    float gr = (l < 16) ? s0r : s1r;
    float gz = (l < 16) ? s0z : s1z;
    float gn = (l < 16) ? s0n : s1n;
    float hp = hn_sm[1][myd];
    float gir = 0.f, giz = 0.f, gin = 0.f;
    if (ml == 0) {
        gir = __ldg(&d_Gi[myd]);
        giz = __ldg(&d_Gi[M_DIM + myd]);
        gin = __ldg(&d_Gi[2 * M_DIM + myd]);
    }

    __syncthreads();
    CLUSTER_SYNC();

    for (int t = 0; t < T_STEPS; t++) {
        const int tb = t & 1;

        // ---------- gates (verbatim expressions) on lanes 0, 16 ----------
        float hnewv = 0.f;
        if (ml == 0) {
            float hr = gr + bhr, hz = gz + bhz, hn = gn + bhn;
            float rg = 1.f / (1.f + expf(-(gir + hr)));
            float zg = 1.f / (1.f + expf(-(giz + hz)));
            float ng = tanhf(gin + rg * hn);
            hnewv = (1.f - zg) * ng + zg * hp;
        }
        const float v0 = __shfl_sync(0xFFFFFFFFu, hnewv, 0);
        const float v1 = __shfl_sync(0xFFFFFFFFu, hnewv, 16);

        // ---------- broadcast h_new to all CTAs ----------
        dsmem_st_f32(&hn_sm[tb][myd], (unsigned)ml, (l < 16) ? v0 : v1);
        CLUSTER_ARRIVE();                 // sync1 arrive (release covers our stores)

        // prefetch Gi(t+1) into registers (consumed next iteration)
        float ngir = 0.f, ngiz = 0.f, ngin = 0.f;
        if (ml == 0 && t + 1 < T_STEPS) {
            const float* g = &d_Gi[(size_t)(t + 1) * G3];
            ngir = __ldg(&g[myd]);
            ngiz = __ldg(&g[M_DIM + myd]);
            ngin = __ldg(&g[2 * M_DIM + myd]);
        }
        CLUSTER_WAIT();                   // sync1 wait: hn_sm[tb] complete everywhere

        // ---------- logits + keys ----------
        #pragma unroll
        for (int cch = 0; cch < 4; cch++) nv[cch] = *(const float4*)&hn_sm[tb][cch * 128 + 4 * l];
        float acc0 = 0.f, acc1 = 0.f;
        #pragma unroll
        for (int cch = 0; cch < 4; cch++) {
            acc0 = fmaf(cw0[cch].x, nv[cch].x, fmaf(cw0[cch].y, nv[cch].y,
                   fmaf(cw0[cch].z, nv[cch].z, fmaf(cw0[cch].w, nv[cch].w, acc0))));
        }
        #pragma unroll
        for (int o = 16; o > 0; o >>= 1) acc0 += __shfl_xor_sync(0xFFFFFFFFu, acc0, o);
        #pragma unroll
        for (int cch = 0; cch < 4; cch++) {
            acc1 = fmaf(cw1[cch].x, nv[cch].x, fmaf(cw1[cch].y, nv[cch].y,
                   fmaf(cw1[cch].z, nv[cch].z, fmaf(cw1[cch].w, nv[cch].w, acc1))));
        }
        #pragma unroll
        for (int o = 16; o > 0; o >>= 1) acc1 += __shfl_xor_sync(0xFFFFFFFFu, acc1, o);

        if (l == 0) {
            unsigned int u0 = __float_as_uint(acc0 + cb0);
            u0 ^= (u0 & 0x80000000u) ? 0xFFFFFFFFu : 0x80000000u;
            unsigned long long k0 = ((unsigned long long)u0 << 32) | (unsigned int)(1023 - d0);
            unsigned int u1 = __float_as_uint(acc1 + cb1);
            u1 ^= (u1 & 0x80000000u) ? 0xFFFFFFFFu : 0x80000000u;
            unsigned long long k1 = ((unsigned long long)u1 << 32) | (unsigned int)(1023 - d1);
            wkey_sm[w] = (k0 > k1) ? k0 : k1;
        }
        __syncthreads();
        if (w == 0) {
            unsigned long long k = (l < 16) ? wkey_sm[l] : 0ull;
            #pragma unroll
            for (int o = 16; o > 0; o >>= 1) {
                unsigned long long ok = __shfl_xor_sync(0xFFFFFFFFu, k, o);
                if (ok > k) k = ok;
            }
            if (l < CSZ) dsmem_st_u64(&ckey_sm[c], (unsigned)l, k);
        }
        CLUSTER_ARRIVE();                 // sync2 arrive

        // ---------- speculative W_hh @ h_new (hides sync2 wait) ----------
        s0z = dot_sm(&W_sm[(0 * DPC + w)      * M_DIM]);
        s0n = dot_sm(&W_sm[(1 * DPC + w)      * M_DIM]);
        s1z = dot_sm(&W_sm[(0 * DPC + 16 + w) * M_DIM]);
        s1n = dot_sm(&W_sm[(1 * DPC + 16 + w) * M_DIM]);
        s0r = dot_rg(wr0);
        s1r = dot_rg(wr1);

        CLUSTER_WAIT();                   // sync2 wait: all 16 CTA keys visible

        // ---------- decision (redundant, identical everywhere) ----------
        if (w == 0) {
            unsigned long long k = (l < CSZ) ? ckey_sm[l] : 0ull;
            #pragma unroll
            for (int o = 16; o > 0; o >>= 1) {
                unsigned long long ok = __shfl_xor_sync(0xFFFFFFFFu, k, o);
                if (ok > k) k = ok;
            }
            if (l == 0) {
                int q   = 1023 - (int)(k & 0xFFFFFFFFull);
                int has = (q > 0) && (written_sm[q] != 0);
                if (q > 0) written_sm[q] = 1;
                dec_sm = (q << 1) | has;
            }
        }
        __syncthreads();
        const int dec = dec_sm;
        const int q   = dec >> 1;
        const int has = dec & 1;

        // ---------- select next gate inputs + cache maintenance ----------
        const float s_r = (l < 16) ? s0r : s1r;
        const float s_z = (l < 16) ? s0z : s1z;
        const float s_n = (l < 16) ? s0n : s1n;
        const float hnw = (l < 16) ? v0  : v1;

        if (ml == 0) {
            if (has) {   // CTA-private slices: written by this CTA at the write step
                gr = __ldg(&d_Gc[(size_t)q * G3 + 3 * myd + 0]);
                gz = __ldg(&d_Gc[(size_t)q * G3 + 3 * myd + 1]);
                gn = __ldg(&d_Gc[(size_t)q * G3 + 3 * myd + 2]);
                hp = __ldg(&d_M [(size_t)q * M_DIM + myd]);
            } else {
                gr = s_r; gz = s_z; gn = s_n; hp = hnw;
            }
            if (!has && q > 0) {   // first write: cache gh(h_new) + memory value
                d_Gc[(size_t)q * G3 + 3 * myd + 0] = s_r;
                d_Gc[(size_t)q * G3 + 3 * myd + 1] = s_z;
                d_Gc[(size_t)q * G3 + 3 * myd + 2] = s_n;
                d_M [(size_t)q * M_DIM + myd]      = hnw;
            }
            gir = ngir; giz = ngiz; gin = ngin;
        }

        // ---------- history writeback, duty rotated across CTAs ----------
        if (c == (t & (CSZ - 1))) {
            float hv_out = has ? ldcg_f(&d_M[(size_t)q * M_DIM + tid]) : hn_sm[tb][tid];
            d_H[(size_t)t * M_DIM + tid] = hv_out;
        }
    }

    CLUSTER_SYNC();   // no CTA exits while peers may still touch its SMEM
}

extern "C" void kernel_launch(void* const* d_in, const int* in_sizes, int n_in,
                              void* d_out, int out_size)
{
    const float* X    = (const float*)d_in[0];
    const float* h0   = (const float*)d_in[1];
    const float* W_ih = (const float*)d_in[2];
    const float* W_hh = (const float*)d_in[3];
    const float* b_ih = (const float*)d_in[4];
    const float* b_hh = (const float*)d_in[5];
    const float* C_w  = (const float*)d_in[6];
    const float* C_b  = (const float*)d_in[7];
    const float* V_w  = (const float*)d_in[8];
    const float* V_b  = (const float*)d_in[9];
    float* Y = (float*)d_out;

    float* Gi; cudaGetSymbolAddress((void**)&Gi, d_Gi);
    float* H;  cudaGetSymbolAddress((void**)&H,  d_H);

    // 1) Gi = X @ W_ih^T + b_ih
    {
        dim3 blk(32, 32), grid(G3 / 32, T_STEPS / 32);
        gemm32_nt<<<grid, blk>>>(X, W_ih, b_ih, Gi, T_STEPS, G3, N_DIM);
    }
    // 2) clustered recurrent loop (one 16-CTA cluster, split HW barriers + speculation)
    {
        const int smem = 2 * DPC * M_DIM * (int)sizeof(float);   // 131072
        cudaFuncSetAttribute(dmm_rec, cudaFuncAttributeNonPortableClusterSizeAllowed, 1);
        cudaFuncSetAttribute(dmm_rec, cudaFuncAttributeMaxDynamicSharedMemorySize, smem);
        cudaLaunchConfig_t cfg = {};
        cfg.gridDim  = dim3(CSZ, 1, 1);
        cfg.blockDim = dim3(NTHR, 1, 1);
        cfg.dynamicSmemBytes = smem;
        cfg.stream = 0;
        cudaLaunchAttribute at[1];
        at[0].id = cudaLaunchAttributeClusterDimension;
        at[0].val.clusterDim.x = CSZ;
        at[0].val.clusterDim.y = 1;
        at[0].val.clusterDim.z = 1;
        cfg.attrs = at;
        cfg.numAttrs = 1;
        cudaLaunchKernelEx(&cfg, dmm_rec, h0, W_hh, b_hh, C_w, C_b);
    }
    // 3) Y = H @ V_w^T + V_b
    {
        dim3 blk(32, 32), grid(L_OUT / 32, T_STEPS / 32);
        gemm32_nt<<<grid, blk>>>(H, V_w, V_b, Y, T_STEPS, L_OUT, M_DIM);
    }
}

// round 9
// speedup vs baseline: 1.6250x; 1.3628x over previous
#include <cuda_runtime.h>
#include <cuda_bf16.h>
#include <math.h>

#define T_STEPS 16384
#define N_DIM   256
#define M_DIM   512
#define G3      1536   // 3*M
#define NADDR   512    // K_MEM+1
#define L_OUT   256

#define CSZ     16     // cluster size (CTAs)
#define DPC     32     // h-dims per CTA (512/16)
#define NTHR    512

// ---------------- device scratch (static, no allocation) ----------------
__device__ __align__(16) float d_Gi[T_STEPS * G3];     // X @ W_ih^T + b_ih
__device__ __align__(16) float d_H [T_STEPS * M_DIM];  // h_out history
__device__ __align__(16) float d_M [NADDR * M_DIM];    // memory rows (write-once)
__device__ __align__(16) float d_Gc[NADDR * G3];       // cached gh: [q][3*d + gate]

// ---------------- helpers ----------------
__device__ __forceinline__ float ldcg_f(const float* p) {
    float v; asm volatile("ld.global.cg.f32 %0, [%1];" : "=f"(v) : "l"(p) : "memory"); return v;
}
// st.async: remote SMEM store whose completion is tx-accounted on the remote mbarrier
__device__ __forceinline__ void stasync_f32(float* lptr, unsigned long long* lmbar,
                                            unsigned rank, float v) {
    unsigned la = (unsigned)__cvta_generic_to_shared(lptr);
    unsigned lm = (unsigned)__cvta_generic_to_shared(lmbar);
    unsigned ra, rm;
    asm volatile("mapa.shared::cluster.u32 %0, %1, %2;" : "=r"(ra) : "r"(la), "r"(rank));
    asm volatile("mapa.shared::cluster.u32 %0, %1, %2;" : "=r"(rm) : "r"(lm), "r"(rank));
    asm volatile("st.async.weak.shared::cluster.mbarrier::complete_tx::bytes.b32 [%0], %1, [%2];"
                 :: "r"(ra), "r"(__float_as_uint(v)), "r"(rm) : "memory");
}
__device__ __forceinline__ void stasync_u64(unsigned long long* lptr, unsigned long long* lmbar,
                                            unsigned rank, unsigned long long v) {
    unsigned la = (unsigned)__cvta_generic_to_shared(lptr);
    unsigned lm = (unsigned)__cvta_generic_to_shared(lmbar);
    unsigned ra, rm;
    asm volatile("mapa.shared::cluster.u32 %0, %1, %2;" : "=r"(ra) : "r"(la), "r"(rank));
    asm volatile("mapa.shared::cluster.u32 %0, %1, %2;" : "=r"(rm) : "r"(lm), "r"(rank));
    asm volatile("st.async.weak.shared::cluster.mbarrier::complete_tx::bytes.b64 [%0], %1, [%2];"
                 :: "r"(ra), "l"(v), "r"(rm) : "memory");
}
__device__ __forceinline__ void mbar_init(unsigned long long* m, unsigned cnt) {
    unsigned a = (unsigned)__cvta_generic_to_shared(m);
    asm volatile("mbarrier.init.shared.b64 [%0], %1;" :: "r"(a), "r"(cnt) : "memory");
}
__device__ __forceinline__ void mbar_expect_tx(unsigned long long* m, unsigned bytes) {
    unsigned a = (unsigned)__cvta_generic_to_shared(m);
    asm volatile("mbarrier.arrive.expect_tx.shared.b64 _, [%0], %1;" :: "r"(a), "r"(bytes) : "memory");
}
__device__ __forceinline__ void mbar_wait(unsigned long long* m, unsigned parity) {
    unsigned a = (unsigned)__cvta_generic_to_shared(m);
    unsigned done;
    asm volatile("{\n\t.reg .pred p;\n\t"
                 "mbarrier.try_wait.parity.acquire.cta.shared::cta.b64 p, [%1], %2;\n\t"
                 "selp.b32 %0, 1, 0, p;\n\t}"
                 : "=r"(done) : "r"(a), "r"(parity) : "memory");
    if (!done) {
        asm volatile("{\n\t.reg .pred P1;\n\t"
                     "WL_%=:\n\t"
                     "mbarrier.try_wait.parity.acquire.cta.shared::cta.b64 P1, [%0], %1, 0x989680;\n\t"
                     "@P1 bra.uni WD_%=;\n\t"
                     "bra.uni WL_%=;\n\t"
                     "WD_%=:\n\t}"
                     :: "r"(a), "r"(parity) : "memory");
    }
}
#define CLUSTER_SYNC() do { \
    asm volatile("barrier.cluster.arrive.aligned;" ::: "memory"); \
    asm volatile("barrier.cluster.wait.aligned;"   ::: "memory"); } while (0)

// ---------------- textbook 32x32 tiled NT GEMM (known good) ----------------
__global__ __launch_bounds__(1024) void gemm32_nt(
    const float* __restrict__ A, const float* __restrict__ B,
    const float* __restrict__ bias, float* __restrict__ C,
    int M, int N, int K)
{
    __shared__ float As[32][33];
    __shared__ float Bs[32][33];
    const int bm = blockIdx.y * 32;
    const int bn = blockIdx.x * 32;
    const int tx = threadIdx.x;
    const int ty = threadIdx.y;
    float acc = 0.f;
    for (int k0 = 0; k0 < K; k0 += 32) {
        As[ty][tx] = A[(size_t)(bm + ty) * K + k0 + tx];
        Bs[ty][tx] = B[(size_t)(bn + ty) * K + k0 + tx];
        __syncthreads();
        #pragma unroll
        for (int k = 0; k < 32; k++)
            acc = fmaf(As[ty][k], Bs[tx][k], acc);
        __syncthreads();
    }
    C[(size_t)(bm + ty) * N + bn + tx] = acc + bias[bn + tx];
}

// ---------------- clustered recurrent kernel: st.async + mbarrier phases ----------------
// One 16-CTA cluster. Warp w owns dims d0=32c+w, d1=32c+16+w and logit rows d0,d1.
// Gate-r + C_w rows in registers; z,n rows in SMEM. No cluster barriers in-loop:
// hn and keys travel via st.async w/ complete_tx; consumers wait on local mbarriers.
// All arithmetic verbatim round-4/6/8 -> trajectory bit-identical.
__global__ __launch_bounds__(NTHR, 1) void dmm_rec(
    const float* __restrict__ h0,
    const float* __restrict__ W_hh,
    const float* __restrict__ b_hh,
    const float* __restrict__ C_w,
    const float* __restrict__ C_b)
{
    extern __shared__ float W_sm[];                 // [2*DPC][512]: z rows, n rows
    __shared__ float hn_sm[2][M_DIM];               // st.async target (double buffer)
    __shared__ unsigned long long wkey_sm[16];
    __shared__ unsigned long long ckey_sm[CSZ];     // st.async target (single buffer)
    __shared__ unsigned char written_w[16][NADDR];  // per-warp replicas of 'written'
    __shared__ unsigned long long mbar_hn, mbar_key;

    const int c   = blockIdx.x;                     // cluster rank (single cluster)
    const int tid = threadIdx.x;
    const int w   = tid >> 5;
    const int l   = tid & 31;
    const int ml  = l & 15;
    const int d0  = DPC * c + w;
    const int d1  = DPC * c + 16 + w;
    const int myd = (l < 16) ? d0 : d1;

    // ---- one-time init ----
    for (int idx = tid; idx < 2 * DPC * M_DIM; idx += NTHR) {
        int g   = idx >> 14;
        int rem = idx & 16383;
        int lr  = rem >> 9;
        int col = rem & 511;
        W_sm[idx] = W_hh[(size_t)((g + 1) * M_DIM + DPC * c + lr) * M_DIM + col];
    }
    for (int idx = tid; idx < 16 * NADDR; idx += NTHR)
        written_w[idx >> 9][idx & 511] = 0;
    if (tid == 0) {
        mbar_init(&mbar_hn, 1);
        mbar_init(&mbar_key, 1);
        asm volatile("fence.mbarrier_init.release.cluster;" ::: "memory");
    }

    float4 wr0[4], wr1[4], cw0[4], cw1[4];
    #pragma unroll
    for (int cch = 0; cch < 4; cch++) {
        wr0[cch] = *(const float4*)&W_hh[(size_t)d0 * M_DIM + cch * 128 + 4 * l];
        wr1[cch] = *(const float4*)&W_hh[(size_t)d1 * M_DIM + cch * 128 + 4 * l];
        cw0[cch] = *(const float4*)&C_w [(size_t)d0 * M_DIM + cch * 128 + 4 * l];
        cw1[cch] = *(const float4*)&C_w [(size_t)d1 * M_DIM + cch * 128 + 4 * l];
    }
    const float cb0 = C_b[d0], cb1 = C_b[d1];
    const float bhr = b_hh[myd], bhz = b_hh[M_DIM + myd], bhn = b_hh[2 * M_DIM + myd];

    // ---- bootstrap: spec dots on h0 ----
    if (tid < M_DIM) hn_sm[1][tid] = h0[tid];
    __syncthreads();

    float4 nv[4];
    #pragma unroll
    for (int cch = 0; cch < 4; cch++) nv[cch] = *(const float4*)&hn_sm[1][cch * 128 + 4 * l];

    auto dot_sm = [&](const float* __restrict__ row) -> float {
        float acc = 0.f;
        #pragma unroll
        for (int cch = 0; cch < 4; cch++) {
            float4 wv = *(const float4*)&row[cch * 128 + 4 * l];
            acc = fmaf(wv.x, nv[cch].x, fmaf(wv.y, nv[cch].y,
                  fmaf(wv.z, nv[cch].z, fmaf(wv.w, nv[cch].w, acc))));
        }
        #pragma unroll
        for (int o = 16; o > 0; o >>= 1) acc += __shfl_xor_sync(0xFFFFFFFFu, acc, o);
        return acc;
    };
    auto dot_rg = [&](const float4* wreg) -> float {
        float acc = 0.f;
        #pragma unroll
        for (int cch = 0; cch < 4; cch++) {
            acc = fmaf(wreg[cch].x, nv[cch].x, fmaf(wreg[cch].y, nv[cch].y,
                  fmaf(wreg[cch].z, nv[cch].z, fmaf(wreg[cch].w, nv[cch].w, acc))));
        }
        #pragma unroll
        for (int o = 16; o > 0; o >>= 1) acc += __shfl_xor_sync(0xFFFFFFFFu, acc, o);
        return acc;
    };

    float s0z = dot_sm(&W_sm[(0 * DPC + w)      * M_DIM]);
    float s0n = dot_sm(&W_sm[(1 * DPC + w)      * M_DIM]);
    float s1z = dot_sm(&W_sm[(0 * DPC + 16 + w) * M_DIM]);
    float s1n = dot_sm(&W_sm[(1 * DPC + 16 + w) * M_DIM]);
    float s0r = dot_rg(wr0);
    float s1r = dot_rg(wr1);

    float gr = (l < 16) ? s0r : s1r;
    float gz = (l < 16) ? s0z : s1z;
    float gn = (l < 16) ? s0n : s1n;
    float hp = hn_sm[1][myd];
    float gir = 0.f, giz = 0.f, gin = 0.f;
    if (ml == 0) {
        gir = __ldg(&d_Gi[myd]);
        giz = __ldg(&d_Gi[M_DIM + myd]);
        gin = __ldg(&d_Gi[2 * M_DIM + myd]);
    }

    __syncthreads();
    CLUSTER_SYNC();   // mbarriers + SMEM init visible cluster-wide before any st.async

    for (int t = 0; t < T_STEPS; t++) {
        const int tb = t & 1;
        const unsigned par = (unsigned)(t & 1);

        // ---------- gates (lanes 0,16), verbatim expressions ----------
        float hnewv = 0.f;
        if (ml == 0) {
            float hr = gr + bhr, hz = gz + bhz, hn = gn + bhn;
            float rg = 1.f / (1.f + expf(-(gir + hr)));
            float zg = 1.f / (1.f + expf(-(giz + hz)));
            float ng = tanhf(gin + rg * hn);
            hnewv = (1.f - zg) * ng + zg * hp;
        }
        const float v0 = __shfl_sync(0xFFFFFFFFu, hnewv, 0);
        const float v1 = __shfl_sync(0xFFFFFFFFu, hnewv, 16);

        // ---------- send h_new: each thread -> rank ml, tx-accounted ----------
        stasync_f32(&hn_sm[tb][myd], &mbar_hn, (unsigned)ml, (l < 16) ? v0 : v1);
        if (tid == 0) mbar_expect_tx(&mbar_hn, M_DIM * 4u);   // 2048 B per phase

        // prefetch Gi(t+1) (hides under hn wait)
        float ngir = 0.f, ngiz = 0.f, ngin = 0.f;
        if (ml == 0 && t + 1 < T_STEPS) {
            const float* g = &d_Gi[(size_t)(t + 1) * G3];
            ngir = __ldg(&g[myd]);
            ngiz = __ldg(&g[M_DIM + myd]);
            ngin = __ldg(&g[2 * M_DIM + myd]);
        }

        mbar_wait(&mbar_hn, par);   // all 512 dims landed locally

        // ---------- logits for d0,d1 ----------
        #pragma unroll
        for (int cch = 0; cch < 4; cch++) nv[cch] = *(const float4*)&hn_sm[tb][cch * 128 + 4 * l];
        float acc0 = 0.f, acc1 = 0.f;
        #pragma unroll
        for (int cch = 0; cch < 4; cch++) {
            acc0 = fmaf(cw0[cch].x, nv[cch].x, fmaf(cw0[cch].y, nv[cch].y,
                   fmaf(cw0[cch].z, nv[cch].z, fmaf(cw0[cch].w, nv[cch].w, acc0))));
        }
        #pragma unroll
        for (int o = 16; o > 0; o >>= 1) acc0 += __shfl_xor_sync(0xFFFFFFFFu, acc0, o);
        #pragma unroll
        for (int cch = 0; cch < 4; cch++) {
            acc1 = fmaf(cw1[cch].x, nv[cch].x, fmaf(cw1[cch].y, nv[cch].y,
                   fmaf(cw1[cch].z, nv[cch].z, fmaf(cw1[cch].w, nv[cch].w, acc1))));
        }
        #pragma unroll
        for (int o = 16; o > 0; o >>= 1) acc1 += __shfl_xor_sync(0xFFFFFFFFu, acc1, o);

        if (l == 0) {
            unsigned int u0 = __float_as_uint(acc0 + cb0);
            u0 ^= (u0 & 0x80000000u) ? 0xFFFFFFFFu : 0x80000000u;
            unsigned long long k0 = ((unsigned long long)u0 << 32) | (unsigned int)(1023 - d0);
            unsigned int u1 = __float_as_uint(acc1 + cb1);
            u1 ^= (u1 & 0x80000000u) ? 0xFFFFFFFFu : 0x80000000u;
            unsigned long long k1 = ((unsigned long long)u1 << 32) | (unsigned int)(1023 - d1);
            wkey_sm[w] = (k0 > k1) ? k0 : k1;
        }
        __syncthreads();
        if (tid == 0) mbar_expect_tx(&mbar_key, CSZ * 8u);    // 128 B per phase
        if (w == 0) {
            unsigned long long k = (l < 16) ? wkey_sm[l] : 0ull;
            #pragma unroll
            for (int o = 16; o > 0; o >>= 1) {
                unsigned long long ok = __shfl_xor_sync(0xFFFFFFFFu, k, o);
                if (ok > k) k = ok;
            }
            if (l < CSZ) stasync_u64(&ckey_sm[c], &mbar_key, (unsigned)l, k);
        }

        // ---------- speculative W_hh @ h_new (hides the key exchange) ----------
        s0z = dot_sm(&W_sm[(0 * DPC + w)      * M_DIM]);
        s0n = dot_sm(&W_sm[(1 * DPC + w)      * M_DIM]);
        s1z = dot_sm(&W_sm[(0 * DPC + 16 + w) * M_DIM]);
        s1n = dot_sm(&W_sm[(1 * DPC + 16 + w) * M_DIM]);
        s0r = dot_rg(wr0);
        s1r = dot_rg(wr1);

        mbar_wait(&mbar_key, par);   // all 16 CTA keys landed locally

        // ---------- per-warp redundant decision (no syncthreads) ----------
        unsigned long long kk = (l < CSZ) ? ckey_sm[l] : 0ull;
        #pragma unroll
        for (int o = 16; o > 0; o >>= 1) {
            unsigned long long ok = __shfl_xor_sync(0xFFFFFFFFu, kk, o);
            if (ok > kk) kk = ok;
        }
        const int q   = 1023 - (int)(kk & 0xFFFFFFFFull);
        const int has = (q > 0) && (written_w[w][q] != 0);
        __syncwarp();
        if (l == 0 && q > 0) written_w[w][q] = 1;

        // ---------- select next gate inputs + cache maintenance ----------
        const float s_r = (l < 16) ? s0r : s1r;
        const float s_z = (l < 16) ? s0z : s1z;
        const float s_n = (l < 16) ? s0n : s1n;
        const float hnw = (l < 16) ? v0  : v1;

        if (ml == 0) {
            if (has) {   // CTA-private cached slices (immutable after write)
                gr = __ldg(&d_Gc[(size_t)q * G3 + 3 * myd + 0]);
                gz = __ldg(&d_Gc[(size_t)q * G3 + 3 * myd + 1]);
                gn = __ldg(&d_Gc[(size_t)q * G3 + 3 * myd + 2]);
                hp = __ldg(&d_M [(size_t)q * M_DIM + myd]);
            } else {
                gr = s_r; gz = s_z; gn = s_n; hp = hnw;
            }
            if (!has && q > 0) {
                d_Gc[(size_t)q * G3 + 3 * myd + 0] = s_r;
                d_Gc[(size_t)q * G3 + 3 * myd + 1] = s_z;
                d_Gc[(size_t)q * G3 + 3 * myd + 2] = s_n;
                d_M [(size_t)q * M_DIM + myd]      = hnw;
            }
            gir = ngir; giz = ngiz; gin = ngin;
        }

        // ---------- history writeback, duty rotated ----------
        if (c == (t & (CSZ - 1))) {
            float hv_out = has ? ldcg_f(&d_M[(size_t)q * M_DIM + tid]) : hn_sm[tb][tid];
            d_H[(size_t)t * M_DIM + tid] = hv_out;
        }
    }

    CLUSTER_SYNC();   // keep SMEM alive until all peers are done
}

extern "C" void kernel_launch(void* const* d_in, const int* in_sizes, int n_in,
                              void* d_out, int out_size)
{
    const float* X    = (const float*)d_in[0];
    const float* h0   = (const float*)d_in[1];
    const float* W_ih = (const float*)d_in[2];
    const float* W_hh = (const float*)d_in[3];
    const float* b_ih = (const float*)d_in[4];
    const float* b_hh = (const float*)d_in[5];
    const float* C_w  = (const float*)d_in[6];
    const float* C_b  = (const float*)d_in[7];
    const float* V_w  = (const float*)d_in[8];
    const float* V_b  = (const float*)d_in[9];
    float* Y = (float*)d_out;

    float* Gi; cudaGetSymbolAddress((void**)&Gi, d_Gi);
    float* H;  cudaGetSymbolAddress((void**)&H,  d_H);

    // 1) Gi = X @ W_ih^T + b_ih
    {
        dim3 blk(32, 32), grid(G3 / 32, T_STEPS / 32);
        gemm32_nt<<<grid, blk>>>(X, W_ih, b_ih, Gi, T_STEPS, G3, N_DIM);
    }
    // 2) clustered recurrent loop (st.async + mbarrier phase sync)
    {
        const int smem = 2 * DPC * M_DIM * (int)sizeof(float);   // 131072
        cudaFuncSetAttribute(dmm_rec, cudaFuncAttributeNonPortableClusterSizeAllowed, 1);
        cudaFuncSetAttribute(dmm_rec, cudaFuncAttributeMaxDynamicSharedMemorySize, smem);
        cudaLaunchConfig_t cfg = {};
        cfg.gridDim  = dim3(CSZ, 1, 1);
        cfg.blockDim = dim3(NTHR, 1, 1);
        cfg.dynamicSmemBytes = smem;
        cfg.stream = 0;
        cudaLaunchAttribute at[1];
        at[0].id = cudaLaunchAttributeClusterDimension;
        at[0].val.clusterDim.x = CSZ;
        at[0].val.clusterDim.y = 1;
        at[0].val.clusterDim.z = 1;
        cfg.attrs = at;
        cfg.numAttrs = 1;
        cudaLaunchKernelEx(&cfg, dmm_rec, h0, W_hh, b_hh, C_w, C_b);
    }
    // 3) Y = H @ V_w^T + V_b
    {
        dim3 blk(32, 32), grid(L_OUT / 32, T_STEPS / 32);
        gemm32_nt<<<grid, blk>>>(H, V_w, V_b, Y, T_STEPS, L_OUT, M_DIM);
    }
}

// round 10
// speedup vs baseline: 1.7803x; 1.0955x over previous
#include <cuda_runtime.h>
#include <cuda_bf16.h>
#include <math.h>

#define T_STEPS 16384
#define N_DIM   256
#define M_DIM   512
#define G3      1536   // 3*M
#define NADDR   512    // K_MEM+1
#define L_OUT   256

#define CSZ     16     // cluster size (CTAs)
#define DPC     32     // h-dims per CTA (512/16)
#define NTHR    512

// ---------------- device scratch (static, no allocation) ----------------
__device__ __align__(16) float d_Gi[T_STEPS * G3];     // X @ W_ih^T + b_ih
__device__ __align__(16) float d_H [T_STEPS * M_DIM];  // h_out history
__device__ __align__(16) float d_M [NADDR * M_DIM];    // memory rows (write-once)
__device__ __align__(16) float d_Gc[NADDR * G3];       // cached gh: [q][3*d + gate]

// ---------------- helpers ----------------
__device__ __forceinline__ float ldcg_f(const float* p) {
    float v; asm volatile("ld.global.cg.f32 %0, [%1];" : "=f"(v) : "l"(p) : "memory"); return v;
}
__device__ __forceinline__ void stasync_u64(unsigned long long* lptr, unsigned long long* lmbar,
                                            unsigned rank, unsigned long long v) {
    unsigned la = (unsigned)__cvta_generic_to_shared(lptr);
    unsigned lm = (unsigned)__cvta_generic_to_shared(lmbar);
    unsigned ra, rm;
    asm volatile("mapa.shared::cluster.u32 %0, %1, %2;" : "=r"(ra) : "r"(la), "r"(rank));
    asm volatile("mapa.shared::cluster.u32 %0, %1, %2;" : "=r"(rm) : "r"(lm), "r"(rank));
    asm volatile("st.async.weak.shared::cluster.mbarrier::complete_tx::bytes.b64 [%0], %1, [%2];"
                 :: "r"(ra), "l"(v), "r"(rm) : "memory");
}
// bulk SMEM->remote-SMEM copy, completion tx-accounted on the REMOTE mbarrier
__device__ __forceinline__ void bulk_s2s(float* ldst, const float* lsrc,
                                         unsigned long long* lmbar,
                                         unsigned rank, unsigned bytes) {
    unsigned ld = (unsigned)__cvta_generic_to_shared(ldst);
    unsigned ls = (unsigned)__cvta_generic_to_shared(lsrc);
    unsigned lm = (unsigned)__cvta_generic_to_shared(lmbar);
    unsigned rd, rm;
    asm volatile("mapa.shared::cluster.u32 %0, %1, %2;" : "=r"(rd) : "r"(ld), "r"(rank));
    asm volatile("mapa.shared::cluster.u32 %0, %1, %2;" : "=r"(rm) : "r"(lm), "r"(rank));
    asm volatile("cp.async.bulk.shared::cluster.shared::cta.mbarrier::complete_tx::bytes "
                 "[%0], [%1], %2, [%3];"
                 :: "r"(rd), "r"(ls), "r"(bytes), "r"(rm) : "memory");
}
__device__ __forceinline__ void mbar_init(unsigned long long* m, unsigned cnt) {
    unsigned a = (unsigned)__cvta_generic_to_shared(m);
    asm volatile("mbarrier.init.shared.b64 [%0], %1;" :: "r"(a), "r"(cnt) : "memory");
}
__device__ __forceinline__ void mbar_expect_tx(unsigned long long* m, unsigned bytes) {
    unsigned a = (unsigned)__cvta_generic_to_shared(m);
    asm volatile("mbarrier.arrive.expect_tx.shared.b64 _, [%0], %1;" :: "r"(a), "r"(bytes) : "memory");
}
__device__ __forceinline__ void mbar_wait(unsigned long long* m, unsigned parity) {
    unsigned a = (unsigned)__cvta_generic_to_shared(m);
    unsigned done;
    asm volatile("{\n\t.reg .pred p;\n\t"
                 "mbarrier.try_wait.parity.acquire.cta.shared::cta.b64 p, [%1], %2;\n\t"
                 "selp.b32 %0, 1, 0, p;\n\t}"
                 : "=r"(done) : "r"(a), "r"(parity) : "memory");
    if (!done) {
        asm volatile("{\n\t.reg .pred P1;\n\t"
                     "WL_%=:\n\t"
                     "mbarrier.try_wait.parity.acquire.cta.shared::cta.b64 P1, [%0], %1, 0x989680;\n\t"
                     "@P1 bra.uni WD_%=;\n\t"
                     "bra.uni WL_%=;\n\t"
                     "WD_%=:\n\t}"
                     :: "r"(a), "r"(parity) : "memory");
    }
}
#define CLUSTER_SYNC() do { \
    asm volatile("barrier.cluster.arrive.aligned;" ::: "memory"); \
    asm volatile("barrier.cluster.wait.aligned;"   ::: "memory"); } while (0)

// ---------------- textbook 32x32 tiled NT GEMM (known good) ----------------
__global__ __launch_bounds__(1024) void gemm32_nt(
    const float* __restrict__ A, const float* __restrict__ B,
    const float* __restrict__ bias, float* __restrict__ C,
    int M, int N, int K)
{
    __shared__ float As[32][33];
    __shared__ float Bs[32][33];
    const int bm = blockIdx.y * 32;
    const int bn = blockIdx.x * 32;
    const int tx = threadIdx.x;
    const int ty = threadIdx.y;
    float acc = 0.f;
    for (int k0 = 0; k0 < K; k0 += 32) {
        As[ty][tx] = A[(size_t)(bm + ty) * K + k0 + tx];
        Bs[ty][tx] = B[(size_t)(bn + ty) * K + k0 + tx];
        __syncthreads();
        #pragma unroll
        for (int k = 0; k < 32; k++)
            acc = fmaf(As[ty][k], Bs[tx][k], acc);
        __syncthreads();
    }
    C[(size_t)(bm + ty) * N + bn + tx] = acc + bias[bn + tx];
}

// ---------------- clustered recurrent kernel: bulk S2S hn exchange ----------------
// One 16-CTA cluster. Warp w owns dims d0=32c+w, d1=32c+16+w and logit rows d0,d1.
// h_new slice staged contiguously, delivered to all ranks via 16x cp.async.bulk
// (128B each) with mbarrier tx accounting. Keys via 16x st.async.b64.
// All arithmetic verbatim -> trajectory bit-identical to rounds 4/6/8/9.
__global__ __launch_bounds__(NTHR, 1) void dmm_rec(
    const float* __restrict__ h0,
    const float* __restrict__ W_hh,
    const float* __restrict__ b_hh,
    const float* __restrict__ C_w,
    const float* __restrict__ C_b)
{
    extern __shared__ float W_sm[];                 // [2*DPC][512]: z rows, n rows
    __shared__ __align__(16) float hn_sm[2][M_DIM]; // bulk-copy target (double buffer)
    __shared__ __align__(16) float stage_sm[2][DPC];// local h_new slice (bulk source)
    __shared__ unsigned long long wkey_sm[16];
    __shared__ unsigned long long ckey_sm[CSZ];     // st.async target
    __shared__ unsigned char written_w[16][NADDR];  // per-warp replicas of 'written'
    __shared__ unsigned long long mbar_hn, mbar_key;

    const int c   = blockIdx.x;                     // cluster rank (single cluster)
    const int tid = threadIdx.x;
    const int w   = tid >> 5;
    const int l   = tid & 31;
    const int ml  = l & 15;
    const int d0  = DPC * c + w;
    const int d1  = DPC * c + 16 + w;
    const int myd = (l < 16) ? d0 : d1;

    // ---- one-time init ----
    for (int idx = tid; idx < 2 * DPC * M_DIM; idx += NTHR) {
        int g   = idx >> 14;
        int rem = idx & 16383;
        int lr  = rem >> 9;
        int col = rem & 511;
        W_sm[idx] = W_hh[(size_t)((g + 1) * M_DIM + DPC * c + lr) * M_DIM + col];
    }
    for (int idx = tid; idx < 16 * NADDR; idx += NTHR)
        written_w[idx >> 9][idx & 511] = 0;
    if (tid == 0) {
        mbar_init(&mbar_hn, 1);
        mbar_init(&mbar_key, 1);
        asm volatile("fence.mbarrier_init.release.cluster;" ::: "memory");
    }

    float4 wr0[4], wr1[4], cw0[4], cw1[4];
    #pragma unroll
    for (int cch = 0; cch < 4; cch++) {
        wr0[cch] = *(const float4*)&W_hh[(size_t)d0 * M_DIM + cch * 128 + 4 * l];
        wr1[cch] = *(const float4*)&W_hh[(size_t)d1 * M_DIM + cch * 128 + 4 * l];
        cw0[cch] = *(const float4*)&C_w [(size_t)d0 * M_DIM + cch * 128 + 4 * l];
        cw1[cch] = *(const float4*)&C_w [(size_t)d1 * M_DIM + cch * 128 + 4 * l];
    }
    const float cb0 = C_b[d0], cb1 = C_b[d1];
    const float bhr = b_hh[myd], bhz = b_hh[M_DIM + myd], bhn = b_hh[2 * M_DIM + myd];

    // ---- bootstrap: spec dots on h0 ----
    if (tid < M_DIM) hn_sm[1][tid] = h0[tid];
    __syncthreads();

    float4 nv[4];
    #pragma unroll
    for (int cch = 0; cch < 4; cch++) nv[cch] = *(const float4*)&hn_sm[1][cch * 128 + 4 * l];

    auto dot_sm = [&](const float* __restrict__ row) -> float {
        float acc = 0.f;
        #pragma unroll
        for (int cch = 0; cch < 4; cch++) {
            float4 wv = *(const float4*)&row[cch * 128 + 4 * l];
            acc = fmaf(wv.x, nv[cch].x, fmaf(wv.y, nv[cch].y,
                  fmaf(wv.z, nv[cch].z, fmaf(wv.w, nv[cch].w, acc))));
        }
        #pragma unroll
        for (int o = 16; o > 0; o >>= 1) acc += __shfl_xor_sync(0xFFFFFFFFu, acc, o);
        return acc;
    };
    auto dot_rg = [&](const float4* wreg) -> float {
        float acc = 0.f;
        #pragma unroll
        for (int cch = 0; cch < 4; cch++) {
            acc = fmaf(wreg[cch].x, nv[cch].x, fmaf(wreg[cch].y, nv[cch].y,
                  fmaf(wreg[cch].z, nv[cch].z, fmaf(wreg[cch].w, nv[cch].w, acc))));
        }
        #pragma unroll
        for (int o = 16; o > 0; o >>= 1) acc += __shfl_xor_sync(0xFFFFFFFFu, acc, o);
        return acc;
    };

    float s0z = dot_sm(&W_sm[(0 * DPC + w)      * M_DIM]);
    float s0n = dot_sm(&W_sm[(1 * DPC + w)      * M_DIM]);
    float s1z = dot_sm(&W_sm[(0 * DPC + 16 + w) * M_DIM]);
    float s1n = dot_sm(&W_sm[(1 * DPC + 16 + w) * M_DIM]);
    float s0r = dot_rg(wr0);
    float s1r = dot_rg(wr1);

    float gr = (l < 16) ? s0r : s1r;
    float gz = (l < 16) ? s0z : s1z;
    float gn = (l < 16) ? s0n : s1n;
    float hp = hn_sm[1][myd];
    float gir = 0.f, giz = 0.f, gin = 0.f;
    if (ml == 0) {
        gir = __ldg(&d_Gi[myd]);
        giz = __ldg(&d_Gi[M_DIM + myd]);
        gin = __ldg(&d_Gi[2 * M_DIM + myd]);
    }

    __syncthreads();
    CLUSTER_SYNC();   // mbarriers + SMEM init visible cluster-wide before async traffic

    for (int t = 0; t < T_STEPS; t++) {
        const int tb = t & 1;
        const unsigned par = (unsigned)(t & 1);

        // ---------- gates (lanes 0,16), verbatim expressions ----------
        float hnewv = 0.f;
        if (ml == 0) {
            float hr = gr + bhr, hz = gz + bhz, hn = gn + bhn;
            float rg = 1.f / (1.f + expf(-(gir + hr)));
            float zg = 1.f / (1.f + expf(-(giz + hz)));
            float ng = tanhf(gin + rg * hn);
            hnewv = (1.f - zg) * ng + zg * hp;
            stage_sm[tb][w + ((l < 16) ? 0 : 16)] = hnewv;   // contiguous 128B slice
        }
        const float v0 = __shfl_sync(0xFFFFFFFFu, hnewv, 0);
        const float v1 = __shfl_sync(0xFFFFFFFFu, hnewv, 16);
        __syncthreads();   // stage slice complete

        // ---------- bulk-deliver slice to all 16 ranks (warp 0, 16 x 128B) ----------
        if (tid == 0) mbar_expect_tx(&mbar_hn, M_DIM * 4u);     // 2048 B per phase
        if (w == 0 && l < CSZ) {
            asm volatile("fence.proxy.async.shared::cta;" ::: "memory");
            bulk_s2s(&hn_sm[tb][DPC * c], &stage_sm[tb][0], &mbar_hn,
                     (unsigned)l, DPC * 4u);
        }

        // prefetch Gi(t+1) (hides under hn wait)
        float ngir = 0.f, ngiz = 0.f, ngin = 0.f;
        if (ml == 0 && t + 1 < T_STEPS) {
            const float* g = &d_Gi[(size_t)(t + 1) * G3];
            ngir = __ldg(&g[myd]);
            ngiz = __ldg(&g[M_DIM + myd]);
            ngin = __ldg(&g[2 * M_DIM + myd]);
        }

        mbar_wait(&mbar_hn, par);   // all 16 slices landed locally

        // ---------- logits for d0,d1 ----------
        #pragma unroll
        for (int cch = 0; cch < 4; cch++) nv[cch] = *(const float4*)&hn_sm[tb][cch * 128 + 4 * l];
        float acc0 = 0.f, acc1 = 0.f;
        #pragma unroll
        for (int cch = 0; cch < 4; cch++) {
            acc0 = fmaf(cw0[cch].x, nv[cch].x, fmaf(cw0[cch].y, nv[cch].y,
                   fmaf(cw0[cch].z, nv[cch].z, fmaf(cw0[cch].w, nv[cch].w, acc0))));
        }
        #pragma unroll
        for (int o = 16; o > 0; o >>= 1) acc0 += __shfl_xor_sync(0xFFFFFFFFu, acc0, o);
        #pragma unroll
        for (int cch = 0; cch < 4; cch++) {
            acc1 = fmaf(cw1[cch].x, nv[cch].x, fmaf(cw1[cch].y, nv[cch].y,
                   fmaf(cw1[cch].z, nv[cch].z, fmaf(cw1[cch].w, nv[cch].w, acc1))));
        }
        #pragma unroll
        for (int o = 16; o > 0; o >>= 1) acc1 += __shfl_xor_sync(0xFFFFFFFFu, acc1, o);

        if (l == 0) {
            unsigned int u0 = __float_as_uint(acc0 + cb0);
            u0 ^= (u0 & 0x80000000u) ? 0xFFFFFFFFu : 0x80000000u;
            unsigned long long k0 = ((unsigned long long)u0 << 32) | (unsigned int)(1023 - d0);
            unsigned int u1 = __float_as_uint(acc1 + cb1);
            u1 ^= (u1 & 0x80000000u) ? 0xFFFFFFFFu : 0x80000000u;
            unsigned long long k1 = ((unsigned long long)u1 << 32) | (unsigned int)(1023 - d1);
            wkey_sm[w] = (k0 > k1) ? k0 : k1;
        }
        __syncthreads();
        if (tid == 0) mbar_expect_tx(&mbar_key, CSZ * 8u);      // 128 B per phase
        if (w == 0) {
            unsigned long long k = (l < 16) ? wkey_sm[l] : 0ull;
            #pragma unroll
            for (int o = 16; o > 0; o >>= 1) {
                unsigned long long ok = __shfl_xor_sync(0xFFFFFFFFu, k, o);
                if (ok > k) k = ok;
            }
            if (l < CSZ) stasync_u64(&ckey_sm[c], &mbar_key, (unsigned)l, k);
        }

        // ---------- speculative W_hh @ h_new (hides the key exchange) ----------
        s0z = dot_sm(&W_sm[(0 * DPC + w)      * M_DIM]);
        s0n = dot_sm(&W_sm[(1 * DPC + w)      * M_DIM]);
        s1z = dot_sm(&W_sm[(0 * DPC + 16 + w) * M_DIM]);
        s1n = dot_sm(&W_sm[(1 * DPC + 16 + w) * M_DIM]);
        s0r = dot_rg(wr0);
        s1r = dot_rg(wr1);

        mbar_wait(&mbar_key, par);   // all 16 CTA keys landed locally

        // ---------- per-warp redundant decision (no syncthreads) ----------
        unsigned long long kk = (l < CSZ) ? ckey_sm[l] : 0ull;
        #pragma unroll
        for (int o = 16; o > 0; o >>= 1) {
            unsigned long long ok = __shfl_xor_sync(0xFFFFFFFFu, kk, o);
            if (ok > kk) kk = ok;
        }
        const int q   = 1023 - (int)(kk & 0xFFFFFFFFull);
        const int has = (q > 0) && (written_w[w][q] != 0);
        __syncwarp();
        if (l == 0 && q > 0) written_w[w][q] = 1;

        // ---------- select next gate inputs + cache maintenance ----------
        const float s_r = (l < 16) ? s0r : s1r;
        const float s_z = (l < 16) ? s0z : s1z;
        const float s_n = (l < 16) ? s0n : s1n;
        const float hnw = (l < 16) ? v0  : v1;

        if (ml == 0) {
            if (has) {   // CTA-private cached slices (immutable after write)
                gr = __ldg(&d_Gc[(size_t)q * G3 + 3 * myd + 0]);
                gz = __ldg(&d_Gc[(size_t)q * G3 + 3 * myd + 1]);
                gn = __ldg(&d_Gc[(size_t)q * G3 + 3 * myd + 2]);
                hp = __ldg(&d_M [(size_t)q * M_DIM + myd]);
            } else {
                gr = s_r; gz = s_z; gn = s_n; hp = hnw;
            }
            if (!has && q > 0) {
                d_Gc[(size_t)q * G3 + 3 * myd + 0] = s_r;
                d_Gc[(size_t)q * G3 + 3 * myd + 1] = s_z;
                d_Gc[(size_t)q * G3 + 3 * myd + 2] = s_n;
                d_M [(size_t)q * M_DIM + myd]      = hnw;
            }
            gir = ngir; giz = ngiz; gin = ngin;
        }

        // ---------- history writeback, duty rotated ----------
        if (c == (t & (CSZ - 1))) {
            float hv_out = has ? ldcg_f(&d_M[(size_t)q * M_DIM + tid]) : hn_sm[tb][tid];
            d_H[(size_t)t * M_DIM + tid] = hv_out;
        }
    }

    CLUSTER_SYNC();   // keep SMEM alive until all peers are done
}

extern "C" void kernel_launch(void* const* d_in, const int* in_sizes, int n_in,
                              void* d_out, int out_size)
{
    const float* X    = (const float*)d_in[0];
    const float* h0   = (const float*)d_in[1];
    const float* W_ih = (const float*)d_in[2];
    const float* W_hh = (const float*)d_in[3];
    const float* b_ih = (const float*)d_in[4];
    const float* b_hh = (const float*)d_in[5];
    const float* C_w  = (const float*)d_in[6];
    const float* C_b  = (const float*)d_in[7];
    const float* V_w  = (const float*)d_in[8];
    const float* V_b  = (const float*)d_in[9];
    float* Y = (float*)d_out;

    float* Gi; cudaGetSymbolAddress((void**)&Gi, d_Gi);
    float* H;  cudaGetSymbolAddress((void**)&H,  d_H);

    // 1) Gi = X @ W_ih^T + b_ih
    {
        dim3 blk(32, 32), grid(G3 / 32, T_STEPS / 32);
        gemm32_nt<<<grid, blk>>>(X, W_ih, b_ih, Gi, T_STEPS, G3, N_DIM);
    }
    // 2) clustered recurrent loop (bulk S2S exchange + mbarrier phases)
    {
        const int smem = 2 * DPC * M_DIM * (int)sizeof(float);   // 131072
        cudaFuncSetAttribute(dmm_rec, cudaFuncAttributeNonPortableClusterSizeAllowed, 1);
        cudaFuncSetAttribute(dmm_rec, cudaFuncAttributeMaxDynamicSharedMemorySize, smem);
        cudaLaunchConfig_t cfg = {};
        cfg.gridDim  = dim3(CSZ, 1, 1);
        cfg.blockDim = dim3(NTHR, 1, 1);
        cfg.dynamicSmemBytes = smem;
        cfg.stream = 0;
        cudaLaunchAttribute at[1];
        at[0].id = cudaLaunchAttributeClusterDimension;
        at[0].val.clusterDim.x = CSZ;
        at[0].val.clusterDim.y = 1;
        at[0].val.clusterDim.z = 1;
        cfg.attrs = at;
        cfg.numAttrs = 1;
        cudaLaunchKernelEx(&cfg, dmm_rec, h0, W_hh, b_hh, C_w, C_b);
    }
    // 3) Y = H @ V_w^T + V_b
    {
        dim3 blk(32, 32), grid(L_OUT / 32, T_STEPS / 32);
        gemm32_nt<<<grid, blk>>>(H, V_w, V_b, Y, T_STEPS, L_OUT, M_DIM);
    }
}